// round 9
// baseline (speedup 1.0000x reference)
#include <cuda_runtime.h>
#include <cstdint>
#include <cstddef>

// ---------------------------------------------------------------------------
// Problem constants
// ---------------------------------------------------------------------------
#define B_ROWS 8192
#define MDIM   256
#define NDIM   512
#define NITER  16

// GEMM tiling: CTA 128x128, 8 warps (4 along M x 2 along N), warp tile 32x64
#define MT 128
#define NT 128
#define KC 32               // K per pipeline stage
#define STAGES 3

#define P2 36               // float2 per smem row (pitch) -> bank stride 8, conflict-free
#define STAGE_F2 (128 * P2)                    // 4608 float2 per tile stage
#define B_BASE   (STAGES * STAGE_F2)           // B stages after A stages
#define SMEM_BYTES (2 * STAGES * STAGE_F2 * 8) // 221184 bytes
#define EPI_PITCH 132       // epilogue staging pitch (floats)

// ---------------------------------------------------------------------------
// Device scratch (static __device__ arrays: allocation-free rule)
// ---------------------------------------------------------------------------
__device__ __align__(1024) float2 g_G12[NDIM * NDIM];            // split(D @ S)
__device__ __align__(1024) float2 g_G22[NDIM * NDIM];            // split(D^T)
__device__ __align__(1024) float2 g_GW2[NDIM * MDIM];            // split(D @ W)
__device__ __align__(1024) float2 g_y2[(size_t)B_ROWS * MDIM];   // split(y)
__device__ __align__(1024) float  g_WyD[(size_t)B_ROWS * NDIM];  // fp32 addend
__device__ __align__(1024) float2 g_Sb2[(size_t)B_ROWS * NDIM];  // split(s)
__device__ __align__(1024) float2 g_D2[(size_t)B_ROWS * NDIM];   // split(d_t)

// ---------------------------------------------------------------------------
// PTX helpers (sm_80-level: portable to sm_103 base target)
// ---------------------------------------------------------------------------
__device__ __forceinline__ void cp_async16(uint32_t dst_smem, const void* src) {
    asm volatile("cp.async.cg.shared.global [%0], [%1], 16;"
                 :: "r"(dst_smem), "l"(src) : "memory");
}
__device__ __forceinline__ void cp_commit() {
    asm volatile("cp.async.commit_group;" ::: "memory");
}
template <int N>
__device__ __forceinline__ void cp_wait() {
    asm volatile("cp.async.wait_group %0;" :: "n"(N) : "memory");
}
__device__ __forceinline__ uint32_t f2tf32(float x) {
    uint32_t r;
    asm("cvt.rna.tf32.f32 %0, %1;" : "=r"(r) : "f"(x));
    return r;
}
// x ~= hi + lo, both tf32-valued floats
__device__ __forceinline__ float2 split2(float x) {
    uint32_t h = f2tf32(x);
    float hf = __uint_as_float(h);
    uint32_t l = f2tf32(x - hf);
    return make_float2(hf, __uint_as_float(l));
}
__device__ __forceinline__ void mma_tf32(float* c, const uint32_t* a, const uint32_t* b) {
    asm volatile(
        "mma.sync.aligned.m16n8k8.row.col.f32.tf32.tf32.f32 "
        "{%0,%1,%2,%3},{%4,%5,%6,%7},{%8,%9},{%0,%1,%2,%3};"
        : "+f"(c[0]), "+f"(c[1]), "+f"(c[2]), "+f"(c[3])
        : "r"(a[0]), "r"(a[1]), "r"(a[2]), "r"(a[3]), "r"(b[0]), "r"(b[1]));
}
__device__ __forceinline__ float softthr(float u, float th) {
    return fmaxf(u - th, 0.f) - fmaxf(-u - th, 0.f);
}

// ---------------------------------------------------------------------------
// Small precompute kernels (write split float2 output)
// ---------------------------------------------------------------------------
// C2[n][m] = split( sum_j A[n][j] * X[j][m] )
__global__ void k_small_gemm(const float* __restrict__ A, const float* __restrict__ X,
                             float2* __restrict__ C2, int Mcols, int J) {
    __shared__ float As[16][17];
    __shared__ float Xs[16][17];
    int tx = threadIdx.x, ty = threadIdx.y;
    int m = blockIdx.x * 16 + tx;
    int n = blockIdx.y * 16 + ty;
    float acc = 0.f;
    for (int j0 = 0; j0 < J; j0 += 16) {
        As[ty][tx] = A[(size_t)n * J + j0 + tx];
        Xs[ty][tx] = X[(size_t)(j0 + ty) * Mcols + m];
        __syncthreads();
#pragma unroll
        for (int jj = 0; jj < 16; jj++) acc += As[ty][jj] * Xs[jj][tx];
        __syncthreads();
    }
    C2[(size_t)n * Mcols + m] = split2(acc);
}

// G22[n][k] = split( D[k][n] )
__global__ void k_transpose(const float* __restrict__ D, float2* __restrict__ G22) {
    int k = blockIdx.x * 16 + threadIdx.x;
    int n = blockIdx.y * 16 + threadIdx.y;
    G22[(size_t)n * NDIM + k] = split2(D[(size_t)k * NDIM + n]);
}

// dst2[i] = split(src[i])  (float4-vectorized reads)
__global__ void k_split(const float* __restrict__ src, float2* __restrict__ dst2) {
    size_t i = ((size_t)blockIdx.x * blockDim.x + threadIdx.x) * 4;
    float4 v = *(const float4*)&src[i];
    dst2[i + 0] = split2(v.x);
    dst2[i + 1] = split2(v.y);
    dst2[i + 2] = split2(v.z);
    dst2[i + 3] = split2(v.w);
}

// s2[i] = split( soft_thr(wyd[i], thr) )
__global__ void k_thr0(const float* __restrict__ wyd, float2* __restrict__ s2,
                       const float* __restrict__ thr_p) {
    const float th = thr_p[0];
    size_t i = ((size_t)blockIdx.x * blockDim.x + threadIdx.x) * 4;
    float4 v = *(const float4*)&wyd[i];
    s2[i + 0] = split2(softthr(v.x, th));
    s2[i + 1] = split2(softthr(v.y, th));
    s2[i + 2] = split2(softthr(v.z, th));
    s2[i + 3] = split2(softthr(v.w, th));
}

// ---------------------------------------------------------------------------
// Main 3xtf32 GEMM on pre-split inputs:
//   C_tile(128x128) = A(MTxK) @ Bm(NTxK)^T  with A,B given as (hi,lo) float2
//   mode 0: store fp32 C to outp                      (WyD)
//   mode 1: v = soft_thr(C + wyd, thr); split -> out2 (s)
//   mode 2: v = C; fp32 -> outp AND split -> out2     (d)
// ---------------------------------------------------------------------------
__global__ void __launch_bounds__(256, 1) k_gemm(
    const float2* __restrict__ A2, const float2* __restrict__ B2,
    int K, int mode,
    float* __restrict__ outp, float2* __restrict__ out2,
    const float* __restrict__ wyd, const float* __restrict__ thr_p)
{
    extern __shared__ float2 smf2[];
    float* smf = (float*)smf2;
    const int tid  = threadIdx.x;
    const int lane = tid & 31;
    const int warp = tid >> 5;
    const int warpM = warp & 3;       // rows warpM*32
    const int warpN = warp >> 2;      // cols warpN*64
    const int lr = lane >> 2;         // 0..7
    const int lc = lane & 3;          // 0..3
    const int row0 = blockIdx.x * MT;
    const int col0 = blockIdx.y * NT;
    const int KB = K >> 5;

    float c[2][8][4];
#pragma unroll
    for (int mt = 0; mt < 2; ++mt)
#pragma unroll
        for (int nt = 0; nt < 8; ++nt)
#pragma unroll
            for (int q = 0; q < 4; ++q) c[mt][nt][q] = 0.f;

    const float2* Abase = A2 + (size_t)row0 * K;
    const float2* Bbase = B2 + (size_t)col0 * K;

    // fill one stage: 128 rows x 32 float2 per matrix; 16B = 2 float2 per chunk
    auto fill_stage = [&](int s, int kb) {
        const float2* Ag = Abase + kb * KC;
        const float2* Bg = Bbase + kb * KC;
#pragma unroll
        for (int i = 0; i < 8; ++i) {
            int ch = tid + i * 256;          // 0..2047
            int r  = ch >> 4;                // row 0..127
            int cc = ch & 15;                // 16B chunk in row (2 float2)
            uint32_t da = (uint32_t)__cvta_generic_to_shared(
                &smf2[s * STAGE_F2 + r * P2 + cc * 2]);
            cp_async16(da, Ag + (size_t)r * K + cc * 2);
            uint32_t db = (uint32_t)__cvta_generic_to_shared(
                &smf2[B_BASE + s * STAGE_F2 + r * P2 + cc * 2]);
            cp_async16(db, Bg + (size_t)r * K + cc * 2);
        }
    };

    fill_stage(0, 0); cp_commit();
    fill_stage(1, 1); cp_commit();

    for (int kb = 0; kb < KB; ++kb) {
        cp_wait<STAGES - 2>();
        __syncthreads();

        if (kb + STAGES - 1 < KB) fill_stage((kb + STAGES - 1) % STAGES, kb + STAGES - 1);
        cp_commit();

        const int s = kb % STAGES;
        const float2* sA = &smf2[s * STAGE_F2];
        const float2* sB = &smf2[B_BASE + s * STAGE_F2];

#pragma unroll
        for (int ks = 0; ks < 4; ++ks) {
            uint32_t ah[2][4], al[2][4], bh[8][2], bl[8][2];
            const int kcol = ks * 8 + lc;
#pragma unroll
            for (int mt = 0; mt < 2; ++mt) {
                const int rb = warpM * 32 + mt * 16;
                float2 v0 = sA[(rb + lr)     * P2 + kcol];
                float2 v1 = sA[(rb + lr + 8) * P2 + kcol];
                float2 v2 = sA[(rb + lr)     * P2 + kcol + 4];
                float2 v3 = sA[(rb + lr + 8) * P2 + kcol + 4];
                ah[mt][0] = __float_as_uint(v0.x); al[mt][0] = __float_as_uint(v0.y);
                ah[mt][1] = __float_as_uint(v1.x); al[mt][1] = __float_as_uint(v1.y);
                ah[mt][2] = __float_as_uint(v2.x); al[mt][2] = __float_as_uint(v2.y);
                ah[mt][3] = __float_as_uint(v3.x); al[mt][3] = __float_as_uint(v3.y);
            }
#pragma unroll
            for (int nt = 0; nt < 8; ++nt) {
                const int nb = warpN * 64 + nt * 8;
                float2 w0 = sB[(nb + lr) * P2 + kcol];
                float2 w1 = sB[(nb + lr) * P2 + kcol + 4];
                bh[nt][0] = __float_as_uint(w0.x); bl[nt][0] = __float_as_uint(w0.y);
                bh[nt][1] = __float_as_uint(w1.x); bl[nt][1] = __float_as_uint(w1.y);
            }
            // 3xtf32: c += a_lo*b_hi + a_hi*b_lo + a_hi*b_hi
#pragma unroll
            for (int mt = 0; mt < 2; ++mt)
#pragma unroll
                for (int nt = 0; nt < 8; ++nt) {
                    mma_tf32(c[mt][nt], al[mt], bh[nt]);
                    mma_tf32(c[mt][nt], ah[mt], bl[nt]);
                    mma_tf32(c[mt][nt], ah[mt], bh[nt]);
                }
        }
        __syncthreads();
    }

    cp_wait<0>();
    __syncthreads();

    // ---- epilogue: frags -> smem (pitch 132 floats) -> coalesced global ----
#pragma unroll
    for (int mt = 0; mt < 2; ++mt) {
#pragma unroll
        for (int nt = 0; nt < 8; ++nt) {
            const int r = warpM * 32 + mt * 16 + lr;
            const int col = warpN * 64 + nt * 8 + 2 * lc;
            *(float2*)&smf[r * EPI_PITCH + col]       = make_float2(c[mt][nt][0], c[mt][nt][1]);
            *(float2*)&smf[(r + 8) * EPI_PITCH + col] = make_float2(c[mt][nt][2], c[mt][nt][3]);
        }
    }
    __syncthreads();

    const float th = thr_p[0];
#pragma unroll 4
    for (int i = tid; i < 128 * 32; i += 256) {       // 32 float4 per row
        const int r  = i >> 5;
        const int c4 = i & 31;
        float4 v = *(float4*)&smf[r * EPI_PITCH + c4 * 4];
        const size_t g = (size_t)(row0 + r) * NDIM + col0 + c4 * 4;
        if (mode == 1) {
            const float4 w = *(const float4*)&wyd[g];
            v.x = softthr(v.x + w.x, th);
            v.y = softthr(v.y + w.y, th);
            v.z = softthr(v.z + w.z, th);
            v.w = softthr(v.w + w.w, th);
        }
        if (mode != 1) *(float4*)&outp[g] = v;
        if (mode != 0) {
            float2 s0 = split2(v.x), s1 = split2(v.y), s2 = split2(v.z), s3 = split2(v.w);
            float4* o = (float4*)&out2[g];
            o[0] = make_float4(s0.x, s0.y, s1.x, s1.y);
            o[1] = make_float4(s2.x, s2.y, s3.x, s3.y);
        }
    }
}

// ---------------------------------------------------------------------------
// Host side
// ---------------------------------------------------------------------------
extern "C" void kernel_launch(void* const* d_in, const int* in_sizes, int n_in,
                              void* d_out, int out_size) {
    const float* y   = (const float*)d_in[0];
    const float* S   = (const float*)d_in[1];
    const float* W   = (const float*)d_in[2];
    const float* D   = (const float*)d_in[3];
    const float* thr = (const float*)d_in[4];
    float* out = (float*)d_out;

    void *pG12, *pG22, *pGW2, *py2, *pWyD, *pSb2, *pD2;
    cudaGetSymbolAddress(&pG12, g_G12);
    cudaGetSymbolAddress(&pG22, g_G22);
    cudaGetSymbolAddress(&pGW2, g_GW2);
    cudaGetSymbolAddress(&py2,  g_y2);
    cudaGetSymbolAddress(&pWyD, g_WyD);
    cudaGetSymbolAddress(&pSb2, g_Sb2);
    cudaGetSymbolAddress(&pD2,  g_D2);
    float2* G12 = (float2*)pG12; float2* G22 = (float2*)pG22; float2* GW2 = (float2*)pGW2;
    float2* y2 = (float2*)py2;   float* WyD = (float*)pWyD;
    float2* Sb2 = (float2*)pSb2; float2* D2 = (float2*)pD2;

    cudaFuncSetAttribute(k_gemm, cudaFuncAttributeMaxDynamicSharedMemorySize, SMEM_BYTES);

    const size_t slab = (size_t)B_ROWS * NDIM;

    // d0 = 0
    cudaMemsetAsync(out, 0, slab * sizeof(float));

    // Precompute split B-matrices and split y
    k_transpose<<<dim3(32, 32), dim3(16, 16)>>>(D, G22);
    k_small_gemm<<<dim3(32, 32), dim3(16, 16)>>>(D, S, G12, NDIM, NDIM);
    k_small_gemm<<<dim3(16, 32), dim3(16, 16)>>>(D, W, GW2, MDIM, NDIM);
    k_split<<<(B_ROWS * MDIM / 4) / 256, 256>>>(y, y2);

    const dim3 grid(B_ROWS / MT, NDIM / NT);   // (64, 4)
    const dim3 blk(256);

    // WyD = y @ GW^T   (K = 256), fp32 out
    k_gemm<<<grid, blk, SMEM_BYTES>>>(y2, GW2, MDIM, 0, WyD, nullptr, WyD, thr);

    // t = 0: d0 = 0 -> s = soft_thr(WyD), split
    k_thr0<<<(B_ROWS * NDIM / 4) / 256, 256>>>(WyD, Sb2, thr);
    // d1 = s @ G2^T : fp32 slab + split D2
    k_gemm<<<grid, blk, SMEM_BYTES>>>(Sb2, G22, NDIM, 2, out + slab, D2, WyD, thr);

    for (int t = 1; t < NITER; ++t) {
        // s = soft_thr(d_t @ G1^T + WyD), split only
        k_gemm<<<grid, blk, SMEM_BYTES>>>(D2, G12, NDIM, 1, nullptr, Sb2, WyD, thr);
        // d_{t+1} = s @ G2^T : fp32 slab + split D2
        k_gemm<<<grid, blk, SMEM_BYTES>>>(Sb2, G22, NDIM, 2,
                                          out + (size_t)(t + 1) * slab, D2, WyD, thr);
    }
}

// round 10
// speedup vs baseline: 1.1440x; 1.1440x over previous
#include <cuda_runtime.h>
#include <cstdint>
#include <cstddef>

// ---------------------------------------------------------------------------
// Problem constants
// ---------------------------------------------------------------------------
#define B_ROWS 8192
#define MDIM   256
#define NDIM   512
#define NITER  16

// Persistent-CTA design: 128 CTAs x 512 threads, each CTA owns 64 rows for the
// whole 16-iteration recurrence. Per GEMM: output chunk 64 x 256, K streamed
// in 32-wide blocks through a 2-stage cp.async pipeline.
#define ROWS 64
#define NC   256            // N per chunk (2 chunks cover NDIM=512)
#define KC   32             // K per pipeline stage
#define PA   36             // stage pitch (floats): mod 32 == 4 -> conflict-free frags
#define PS   516            // s_buf pitch (floats): mod 32 == 4
#define PE   260            // epilogue staging pitch

#define A_ST (ROWS * PA)            // 2304 floats per A stage
#define B_ST (NC * PA)              // 9216 floats per B stage
#define S_FLOATS (ROWS * PS)        // 33024
#define A_OFF S_FLOATS
#define B_OFF (A_OFF + 2 * A_ST)    // 37632
#define SM_FLOATS (B_OFF + 2 * B_ST)  // 56064
#define SMEM_BYTES (SM_FLOATS * 4)    // 224256 bytes

// ---------------------------------------------------------------------------
// Device scratch (static __device__ arrays: allocation-free rule)
// ---------------------------------------------------------------------------
__device__ __align__(1024) float g_G1[NDIM * NDIM];            // D @ S
__device__ __align__(1024) float g_G2[NDIM * NDIM];            // D^T (as [n][k])
__device__ __align__(1024) float g_GW[NDIM * MDIM];            // D @ W
__device__ __align__(1024) float g_WyD[(size_t)B_ROWS * NDIM]; // y @ (D W)^T

// ---------------------------------------------------------------------------
// PTX helpers (sm_80-level: portable to sm_103 base target)
// ---------------------------------------------------------------------------
__device__ __forceinline__ void cp_async16(uint32_t dst_smem, const void* src) {
    asm volatile("cp.async.cg.shared.global [%0], [%1], 16;"
                 :: "r"(dst_smem), "l"(src) : "memory");
}
__device__ __forceinline__ void cp_commit() {
    asm volatile("cp.async.commit_group;" ::: "memory");
}
template <int N>
__device__ __forceinline__ void cp_wait() {
    asm volatile("cp.async.wait_group %0;" :: "n"(N) : "memory");
}
__device__ __forceinline__ uint32_t f2tf32(float x) {
    uint32_t r;
    asm("cvt.rna.tf32.f32 %0, %1;" : "=r"(r) : "f"(x));
    return r;
}
__device__ __forceinline__ void tf32_split(float x, uint32_t& hi, uint32_t& lo) {
    hi = f2tf32(x);
    lo = f2tf32(x - __uint_as_float(hi));
}
__device__ __forceinline__ void mma_tf32(float* c, const uint32_t* a, const uint32_t* b) {
    asm volatile(
        "mma.sync.aligned.m16n8k8.row.col.f32.tf32.tf32.f32 "
        "{%0,%1,%2,%3},{%4,%5,%6,%7},{%8,%9},{%0,%1,%2,%3};"
        : "+f"(c[0]), "+f"(c[1]), "+f"(c[2]), "+f"(c[3])
        : "r"(a[0]), "r"(a[1]), "r"(a[2]), "r"(a[3]), "r"(b[0]), "r"(b[1]));
}
__device__ __forceinline__ float softthr(float u, float th) {
    return fmaxf(u - th, 0.f) - fmaxf(-u - th, 0.f);
}

// ---------------------------------------------------------------------------
// Small precompute kernels
// ---------------------------------------------------------------------------
// C[n][m] = sum_j A[n][j] * X[j][m]   (A: 512 x J row-major, X: J x Mcols)
__global__ void k_small_gemm(const float* __restrict__ A, const float* __restrict__ X,
                             float* __restrict__ C, int Mcols, int J) {
    __shared__ float As[16][17];
    __shared__ float Xs[16][17];
    int tx = threadIdx.x, ty = threadIdx.y;
    int m = blockIdx.x * 16 + tx;
    int n = blockIdx.y * 16 + ty;
    float acc = 0.f;
    for (int j0 = 0; j0 < J; j0 += 16) {
        As[ty][tx] = A[(size_t)n * J + j0 + tx];
        Xs[ty][tx] = X[(size_t)(j0 + ty) * Mcols + m];
        __syncthreads();
#pragma unroll
        for (int jj = 0; jj < 16; jj++) acc += As[ty][jj] * Xs[jj][tx];
        __syncthreads();
    }
    C[(size_t)n * Mcols + m] = acc;
}

// G2[n][k] = D[k][n]
__global__ void k_transpose(const float* __restrict__ D, float* __restrict__ G2) {
    int k = blockIdx.x * 16 + threadIdx.x;
    int n = blockIdx.y * 16 + threadIdx.y;
    G2[(size_t)n * NDIM + k] = D[(size_t)k * NDIM + n];
}

// ---------------------------------------------------------------------------
// Persistent ISTA kernel. Each CTA: 64 rows, full recurrence.
// Warp layout per 64x256 chunk: 16 warps = 2 (M) x 8 (N), warp tile 32x32.
// ---------------------------------------------------------------------------
__global__ void __launch_bounds__(512, 1) k_ista(
    const float* __restrict__ y, const float* __restrict__ thr_p,
    float* __restrict__ out,
    const float* __restrict__ G1, const float* __restrict__ G2,
    const float* __restrict__ GW, float* __restrict__ WyD)
{
    extern __shared__ float sm[];
    float* s_buf = sm;                 // 64 x 516 fp32 persistent s tile
    float* Ast   = sm + A_OFF;         // 2 stages, 64 x 36
    float* Bst   = sm + B_OFF;         // 2 stages, 256 x 36
    float* est   = Bst;                // epilogue staging reuses B stages

    const int tid  = threadIdx.x;
    const int lane = tid & 31;
    const int warp = tid >> 5;
    const int wM = warp & 1;           // 2 warps along M (32 rows each)
    const int wN = warp >> 1;          // 8 warps along N (32 cols each)
    const int lr = lane >> 2;          // 0..7
    const int lc = lane & 3;           // 0..3
    const int r0 = blockIdx.x * ROWS;
    const float th = thr_p[0];
    const size_t slab = (size_t)B_ROWS * NDIM;

    // ---- d0 = 0 (slab 0 rows owned by this CTA) ----
    for (int i = tid; i < ROWS * (NDIM / 4); i += 512) {
        int r = i >> 7, c4 = i & 127;
        *(float4*)&out[(size_t)(r0 + r) * NDIM + c4 * 4] = make_float4(0, 0, 0, 0);
    }

    // ---- stage fill helpers ----
    auto fillA = [&](int st, const float* Ag, int lda, int kb) {
        int r = tid >> 3, cc = tid & 7;                   // 64 rows x 8 chunks
        uint32_t d = (uint32_t)__cvta_generic_to_shared(&Ast[st * A_ST + r * PA + cc * 4]);
        cp_async16(d, Ag + (size_t)r * lda + kb * KC + cc * 4);
    };
    auto fillB = [&](int st, const float* Bg, int ldb, int kb) {
#pragma unroll
        for (int i = 0; i < 4; ++i) {
            int ch = tid + i * 512;                       // 256 rows x 8 chunks
            int r = ch >> 3, cc = ch & 7;
            uint32_t d = (uint32_t)__cvta_generic_to_shared(&Bst[st * B_ST + r * PA + cc * 4]);
            cp_async16(d, Bg + (size_t)r * ldb + kb * KC + cc * 4);
        }
    };

    // ---- one k-block of 3xtf32 MMAs; A at (sA, pitch pa, col base ca) ----
    auto mma_stage = [&](const float* sA, int pa, int ca, const float* sB,
                         float (&c)[2][4][4]) {
#pragma unroll
        for (int ks = 0; ks < 4; ++ks) {
            const int kcol = ks * 8 + lc;
            uint32_t ah[2][4], al[2][4], bh[4][2], bl[4][2];
#pragma unroll
            for (int mt = 0; mt < 2; ++mt) {
                const int rb = wM * 32 + mt * 16;
                tf32_split(sA[(rb + lr)     * pa + ca + kcol],     ah[mt][0], al[mt][0]);
                tf32_split(sA[(rb + lr + 8) * pa + ca + kcol],     ah[mt][1], al[mt][1]);
                tf32_split(sA[(rb + lr)     * pa + ca + kcol + 4], ah[mt][2], al[mt][2]);
                tf32_split(sA[(rb + lr + 8) * pa + ca + kcol + 4], ah[mt][3], al[mt][3]);
            }
#pragma unroll
            for (int nt = 0; nt < 4; ++nt) {
                const int nb = wN * 32 + nt * 8;
                tf32_split(sB[(nb + lr) * PA + kcol],     bh[nt][0], bl[nt][0]);
                tf32_split(sB[(nb + lr) * PA + kcol + 4], bh[nt][1], bl[nt][1]);
            }
#pragma unroll
            for (int mt = 0; mt < 2; ++mt)
#pragma unroll
                for (int nt = 0; nt < 4; ++nt) {
                    mma_tf32(c[mt][nt], al[mt], bh[nt]);
                    mma_tf32(c[mt][nt], ah[mt], bl[nt]);
                    mma_tf32(c[mt][nt], ah[mt], bh[nt]);
                }
        }
    };

    // ---- phase1: s_buf = softthr(A @ Bg^T + WyD); prestep also writes WyD ----
    auto phase1 = [&](const float* Ag, int lda, int kdim, const float* Bg, bool prestep) {
        const int KB = kdim / KC;
        for (int nc = 0; nc < 2; ++nc) {
            float c[2][4][4];
#pragma unroll
            for (int mt = 0; mt < 2; ++mt)
#pragma unroll
                for (int nt = 0; nt < 4; ++nt)
#pragma unroll
                    for (int q = 0; q < 4; ++q) c[mt][nt][q] = 0.f;

            const float* Bgc = Bg + (size_t)(nc * NC) * kdim;
            fillA(0, Ag, lda, 0);
            fillB(0, Bgc, kdim, 0);
            cp_commit();
            for (int kb = 0; kb < KB; ++kb) {
                if (kb + 1 < KB) {
                    fillA((kb + 1) & 1, Ag, lda, kb + 1);
                    fillB((kb + 1) & 1, Bgc, kdim, kb + 1);
                    cp_commit();
                    cp_wait<1>();
                } else {
                    cp_wait<0>();
                }
                __syncthreads();
                mma_stage(&Ast[(kb & 1) * A_ST], PA, 0, &Bst[(kb & 1) * B_ST], c);
                __syncthreads();
            }
            // epilogue: u = c (+WyD); s_buf = softthr(u); prestep: WyD = u
#pragma unroll
            for (int mt = 0; mt < 2; ++mt)
#pragma unroll
                for (int nt = 0; nt < 4; ++nt) {
                    const int col = nc * NC + wN * 32 + nt * 8 + 2 * lc;
#pragma unroll
                    for (int half = 0; half < 2; ++half) {
                        const int r = wM * 32 + mt * 16 + lr + half * 8;
                        const size_t g = (size_t)(r0 + r) * NDIM + col;
                        float u0 = c[mt][nt][half * 2 + 0];
                        float u1 = c[mt][nt][half * 2 + 1];
                        if (prestep) {
                            *(float2*)&WyD[g] = make_float2(u0, u1);
                        } else {
                            float2 w = *(const float2*)&WyD[g];
                            u0 += w.x; u1 += w.y;
                        }
                        *(float2*)&s_buf[r * PS + col] =
                            make_float2(softthr(u0, th), softthr(u1, th));
                    }
                }
        }
    };

    // ---- phase2: dst = s_buf @ G2^T (fp32, coalesced via smem staging) ----
    auto phase2 = [&](float* dst) {
        for (int nc = 0; nc < 2; ++nc) {
            float c[2][4][4];
#pragma unroll
            for (int mt = 0; mt < 2; ++mt)
#pragma unroll
                for (int nt = 0; nt < 4; ++nt)
#pragma unroll
                    for (int q = 0; q < 4; ++q) c[mt][nt][q] = 0.f;

            const float* Bgc = G2 + (size_t)(nc * NC) * NDIM;
            fillB(0, Bgc, NDIM, 0);
            cp_commit();
            for (int kb = 0; kb < NDIM / KC; ++kb) {
                if (kb + 1 < NDIM / KC) {
                    fillB((kb + 1) & 1, Bgc, NDIM, kb + 1);
                    cp_commit();
                    cp_wait<1>();
                } else {
                    cp_wait<0>();
                }
                __syncthreads();
                mma_stage(s_buf, PS, kb * KC, &Bst[(kb & 1) * B_ST], c);
                __syncthreads();
            }
            // epilogue: frags -> est (pitch 260) -> coalesced float4 stores
#pragma unroll
            for (int mt = 0; mt < 2; ++mt)
#pragma unroll
                for (int nt = 0; nt < 4; ++nt) {
                    const int col = wN * 32 + nt * 8 + 2 * lc;
                    const int r = wM * 32 + mt * 16 + lr;
                    *(float2*)&est[r * PE + col] =
                        make_float2(c[mt][nt][0], c[mt][nt][1]);
                    *(float2*)&est[(r + 8) * PE + col] =
                        make_float2(c[mt][nt][2], c[mt][nt][3]);
                }
            __syncthreads();
            for (int i = tid; i < ROWS * (NC / 4); i += 512) {
                int r = i >> 6, c4 = i & 63;
                float4 v = *(float4*)&est[r * PE + c4 * 4];
                *(float4*)&dst[(size_t)r * NDIM + nc * NC + c4 * 4] = v;
            }
            __syncthreads();
        }
    };

    // ---- recurrence ----
    // prestep: WyD = y @ GW^T ; s0 = softthr(WyD)
    phase1(y + (size_t)r0 * MDIM, MDIM, MDIM, GW, true);
    __syncthreads();

    for (int t = 1; t <= NITER; ++t) {
        // d_t = s @ G2^T  -> output slab t (this CTA's rows)
        phase2(out + (size_t)t * slab + (size_t)r0 * NDIM);
        __syncthreads();
        if (t < NITER) {
            // s = softthr(d_t @ G1^T + WyD)
            phase1(out + (size_t)t * slab + (size_t)r0 * NDIM, NDIM, NDIM, G1, false);
            __syncthreads();
        }
    }
}

// ---------------------------------------------------------------------------
// Host side
// ---------------------------------------------------------------------------
extern "C" void kernel_launch(void* const* d_in, const int* in_sizes, int n_in,
                              void* d_out, int out_size) {
    const float* y   = (const float*)d_in[0];
    const float* S   = (const float*)d_in[1];
    const float* W   = (const float*)d_in[2];
    const float* D   = (const float*)d_in[3];
    const float* thr = (const float*)d_in[4];
    float* out = (float*)d_out;

    void *pG1, *pG2, *pGW, *pWyD;
    cudaGetSymbolAddress(&pG1, g_G1);
    cudaGetSymbolAddress(&pG2, g_G2);
    cudaGetSymbolAddress(&pGW, g_GW);
    cudaGetSymbolAddress(&pWyD, g_WyD);
    float* G1 = (float*)pG1; float* G2 = (float*)pG2;
    float* GW = (float*)pGW; float* WyD = (float*)pWyD;

    cudaFuncSetAttribute(k_ista, cudaFuncAttributeMaxDynamicSharedMemorySize, SMEM_BYTES);

    // Precompute G2 = D^T, G1 = D@S, GW = D@W
    k_transpose<<<dim3(32, 32), dim3(16, 16)>>>(D, G2);
    k_small_gemm<<<dim3(32, 32), dim3(16, 16)>>>(D, S, G1, NDIM, NDIM);
    k_small_gemm<<<dim3(16, 32), dim3(16, 16)>>>(D, W, GW, MDIM, NDIM);

    // One persistent kernel runs the whole recurrence.
    k_ista<<<B_ROWS / ROWS, 512, SMEM_BYTES>>>(y, thr, out, G1, G2, GW, WyD);
}

// round 11
// speedup vs baseline: 2.0069x; 1.7543x over previous
#include <cuda_runtime.h>
#include <cstdint>
#include <cstddef>

// ---------------------------------------------------------------------------
// Problem constants
// ---------------------------------------------------------------------------
#define B_ROWS 8192
#define MDIM   256
#define NDIM   512
#define NITER  16

// Persistent-CTA: 128 CTAs x 512 threads; CTA owns 64 rows for all iterations.
// Math: packed bf16x2 double-double (hi,lo) -> 3x mma.m16n8k16.bf16.
// Per GEMM: chunk 64 x 256, K in 32-wide blocks (16 k-pairs), 2-stage cp.async.
#define ROWS 64
#define NC   256
#define KC   32            // K elems per block = 16 uint2 k-pairs = 128B row
#define KP   16            // k-pairs per block

// smem layout (uint2 units). XOR swizzle (c ^ ((r&3)<<2)) instead of padding.
#define S_U2   (ROWS * 256)          // 16384 uint2: persistent packed s tile
#define BST_U2 (NC * KP)             // 4096 uint2 per B stage
#define AST_U2 (ROWS * KP)           // 1024 uint2 per A stage
#define SMEM_BYTES ((S_U2 + 2 * BST_U2 + 2 * AST_U2) * 8)   // 212992
#define PE 260                        // epilogue fp32 staging pitch

// ---------------------------------------------------------------------------
// Device scratch (static __device__ arrays: allocation-free rule)
// ---------------------------------------------------------------------------
__device__ __align__(1024) uint2 g_G1p[NDIM * NDIM / 2];           // packed D@S
__device__ __align__(1024) uint2 g_G2p[NDIM * NDIM / 2];           // packed D^T
__device__ __align__(1024) uint2 g_GWp[NDIM * MDIM / 2];           // packed D@W
__device__ __align__(1024) uint2 g_yp[(size_t)B_ROWS * MDIM / 2];  // packed y
__device__ __align__(1024) uint2 g_Dp[(size_t)B_ROWS * NDIM / 2];  // packed d_t
__device__ __align__(1024) float g_WyD[(size_t)B_ROWS * NDIM];     // fp32 addend

// ---------------------------------------------------------------------------
// PTX helpers (sm_80-level: portable to sm_103 base target)
// ---------------------------------------------------------------------------
__device__ __forceinline__ void cp_async16(uint32_t dst_smem, const void* src) {
    asm volatile("cp.async.cg.shared.global [%0], [%1], 16;"
                 :: "r"(dst_smem), "l"(src) : "memory");
}
__device__ __forceinline__ void cp_commit() {
    asm volatile("cp.async.commit_group;" ::: "memory");
}
template <int N>
__device__ __forceinline__ void cp_wait() {
    asm volatile("cp.async.wait_group %0;" :: "n"(N) : "memory");
}
// pack (u0,u1) into bf16x2 hi + bf16x2 lo (lower half = u0)
__device__ __forceinline__ uint2 pack_split(float u0, float u1) {
    uint32_t hi;
    asm("cvt.rn.bf16x2.f32 %0, %1, %2;" : "=r"(hi) : "f"(u1), "f"(u0));
    float h0 = __uint_as_float(hi << 16);
    float h1 = __uint_as_float(hi & 0xFFFF0000u);
    uint32_t lo;
    asm("cvt.rn.bf16x2.f32 %0, %1, %2;" : "=r"(lo) : "f"(u1 - h1), "f"(u0 - h0));
    return make_uint2(hi, lo);
}
__device__ __forceinline__ void mma_bf16(float* c, const uint32_t* a, const uint32_t* b) {
    asm volatile(
        "mma.sync.aligned.m16n8k16.row.col.f32.bf16.bf16.f32 "
        "{%0,%1,%2,%3},{%4,%5,%6,%7},{%8,%9},{%0,%1,%2,%3};"
        : "+f"(c[0]), "+f"(c[1]), "+f"(c[2]), "+f"(c[3])
        : "r"(a[0]), "r"(a[1]), "r"(a[2]), "r"(a[3]), "r"(b[0]), "r"(b[1]));
}
__device__ __forceinline__ float softthr(float u, float th) {
    return fmaxf(u - th, 0.f) - fmaxf(-u - th, 0.f);
}

// ---------------------------------------------------------------------------
// Precompute kernels (pack outputs as bf16x2 hi/lo pairs along k)
// ---------------------------------------------------------------------------
// Cp[n][m-pair] = pack( sum_j A[n][j]*X[j][m] ) ; A: 512 x J, X: J x Mcols
__global__ void k_small_gemm_pack(const float* __restrict__ A, const float* __restrict__ X,
                                  uint2* __restrict__ Cp, int Mcols, int J) {
    __shared__ float As[16][17];
    __shared__ float Xs[16][17];
    int tx = threadIdx.x, ty = threadIdx.y;
    int m = blockIdx.x * 16 + tx;
    int n = blockIdx.y * 16 + ty;
    float acc = 0.f;
    for (int j0 = 0; j0 < J; j0 += 16) {
        As[ty][tx] = A[(size_t)n * J + j0 + tx];
        Xs[ty][tx] = X[(size_t)(j0 + ty) * Mcols + m];
        __syncthreads();
#pragma unroll
        for (int jj = 0; jj < 16; jj++) acc += As[ty][jj] * Xs[jj][tx];
        __syncthreads();
    }
    float other = __shfl_xor_sync(0xffffffffu, acc, 1);
    if (!(tx & 1))
        Cp[(size_t)n * (Mcols / 2) + m / 2] = pack_split(acc, other);
}

// G2p[n][kp] = pack( D[2kp][n], D[2kp+1][n] )
__global__ void k_transpose_pack(const float* __restrict__ D, uint2* __restrict__ G2p) {
    int kp = blockIdx.x * 16 + threadIdx.x;
    int n  = blockIdx.y * 16 + threadIdx.y;
    float u0 = D[(size_t)(2 * kp) * NDIM + n];
    float u1 = D[(size_t)(2 * kp + 1) * NDIM + n];
    G2p[(size_t)n * (NDIM / 2) + kp] = pack_split(u0, u1);
}

// dst[i] = pack(src[2i], src[2i+1])
__global__ void k_split_pack(const float* __restrict__ src, uint2* __restrict__ dst) {
    size_t i = (size_t)blockIdx.x * blockDim.x + threadIdx.x;
    float2 v = ((const float2*)src)[i];
    dst[i] = pack_split(v.x, v.y);
}

// ---------------------------------------------------------------------------
// Persistent ISTA kernel. 16 warps = 2(M) x 8(N), warp tile 32x32.
// ---------------------------------------------------------------------------
__global__ void __launch_bounds__(512, 1) k_ista(
    const float* __restrict__ thr_p, float* __restrict__ out,
    const uint2* __restrict__ G1p, const uint2* __restrict__ G2p,
    const uint2* __restrict__ GWp, const uint2* __restrict__ yp,
    uint2* __restrict__ Dp, float* __restrict__ WyD)
{
    extern __shared__ uint2 smu[];
    uint2* s2   = smu;                         // 64 x 256 packed s (swizzled)
    uint2* BstU = smu + S_U2;                  // 2 x 4096
    uint2* AstU = smu + S_U2 + 2 * BST_U2;     // 2 x 1024
    float* est  = (float*)BstU;                // epilogue fp32 staging overlay

    const int tid  = threadIdx.x;
    const int lane = tid & 31;
    const int warp = tid >> 5;
    const int wM = warp & 1;
    const int wN = warp >> 1;
    const int lr = lane >> 2;
    const int lc = lane & 3;
    const int r0 = blockIdx.x * ROWS;
    const float th = thr_p[0];
    const size_t slab = (size_t)B_ROWS * NDIM;

    // d0 = 0
    for (int i = tid; i < ROWS * (NDIM / 4); i += 512) {
        int r = i >> 7, c4 = i & 127;
        *(float4*)&out[(size_t)(r0 + r) * NDIM + c4 * 4] = make_float4(0, 0, 0, 0);
    }

    // ---- stage fills (16B = 2 uint2 per cp.async; XOR swizzle keeps pairs) ----
    auto fillA = [&](int st, const uint2* Ag, int ldap, int kb) {
        int r = tid >> 3, c2 = tid & 7;
        int cs = (c2 * 2) ^ ((r & 3) << 2);
        uint32_t d = (uint32_t)__cvta_generic_to_shared(&AstU[st * AST_U2 + r * KP + cs]);
        cp_async16(d, Ag + (size_t)r * ldap + kb * KP + c2 * 2);
    };
    auto fillB = [&](int st, const uint2* Bg, int ldbp, int kb) {
#pragma unroll
        for (int i = 0; i < 4; ++i) {
            int ch = tid + i * 512;
            int r = ch >> 3, c2 = ch & 7;
            int cs = (c2 * 2) ^ ((r & 3) << 2);
            uint32_t d = (uint32_t)__cvta_generic_to_shared(&BstU[st * BST_U2 + r * KP + cs]);
            cp_async16(d, Bg + (size_t)r * ldbp + kb * KP + c2 * 2);
        }
    };

    // ---- one k-block of 3-term bf16 MMAs ----
    auto mma_block = [&](auto getA, const uint2* sB, float (&c)[2][4][4]) {
#pragma unroll
        for (int ks = 0; ks < 2; ++ks) {
            const int kb0 = ks * 8 + lc;
            uint32_t ah[2][4], al[2][4], bh[4][2], bl[4][2];
#pragma unroll
            for (int mt = 0; mt < 2; ++mt) {
                const int rb = wM * 32 + mt * 16 + lr;
                uint2 v0 = getA(rb,     kb0);
                uint2 v1 = getA(rb + 8, kb0);
                uint2 v2 = getA(rb,     kb0 + 4);
                uint2 v3 = getA(rb + 8, kb0 + 4);
                ah[mt][0] = v0.x; al[mt][0] = v0.y;
                ah[mt][1] = v1.x; al[mt][1] = v1.y;
                ah[mt][2] = v2.x; al[mt][2] = v2.y;
                ah[mt][3] = v3.x; al[mt][3] = v3.y;
            }
#pragma unroll
            for (int nt = 0; nt < 4; ++nt) {
                const int nb = wN * 32 + nt * 8 + lr;
                uint2 w0 = sB[nb * KP + (kb0 ^ ((nb & 3) << 2))];
                uint2 w1 = sB[nb * KP + ((kb0 + 4) ^ ((nb & 3) << 2))];
                bh[nt][0] = w0.x; bl[nt][0] = w0.y;
                bh[nt][1] = w1.x; bl[nt][1] = w1.y;
            }
#pragma unroll
            for (int mt = 0; mt < 2; ++mt)
#pragma unroll
                for (int nt = 0; nt < 4; ++nt) {
                    mma_bf16(c[mt][nt], al[mt], bh[nt]);
                    mma_bf16(c[mt][nt], ah[mt], bl[nt]);
                    mma_bf16(c[mt][nt], ah[mt], bh[nt]);
                }
        }
    };

    // ---- phase1: s2 = pack(softthr(A @ B^T (+WyD))); prestep writes WyD = u ----
    auto phase1 = [&](const uint2* Ag, int ldap, int KB, const uint2* Bg, int ldbp,
                      bool prestep) {
        for (int nc = 0; nc < 2; ++nc) {
            float c[2][4][4];
#pragma unroll
            for (int mt = 0; mt < 2; ++mt)
#pragma unroll
                for (int nt = 0; nt < 4; ++nt)
#pragma unroll
                    for (int q = 0; q < 4; ++q) c[mt][nt][q] = 0.f;

            const uint2* Bgc = Bg + (size_t)(nc * NC) * ldbp;
            fillA(0, Ag, ldap, 0);
            fillB(0, Bgc, ldbp, 0);
            cp_commit();
            for (int kb = 0; kb < KB; ++kb) {
                if (kb + 1 < KB) {
                    fillA((kb + 1) & 1, Ag, ldap, kb + 1);
                    fillB((kb + 1) & 1, Bgc, ldbp, kb + 1);
                    cp_commit();
                    cp_wait<1>();
                } else {
                    cp_wait<0>();
                }
                __syncthreads();
                const uint2* As = &AstU[(kb & 1) * AST_U2];
                mma_block([&](int r, int kp) {
                    return As[r * KP + (kp ^ ((r & 3) << 2))];
                }, &BstU[(kb & 1) * BST_U2], c);
                __syncthreads();
            }
            // epilogue: u (+WyD) -> softthr -> packed s2 (prestep: store u to WyD)
#pragma unroll
            for (int mt = 0; mt < 2; ++mt)
#pragma unroll
                for (int nt = 0; nt < 4; ++nt) {
                    const int col = nc * NC + wN * 32 + nt * 8 + 2 * lc;
#pragma unroll
                    for (int half = 0; half < 2; ++half) {
                        const int r = wM * 32 + mt * 16 + lr + half * 8;
                        const size_t g = (size_t)(r0 + r) * NDIM + col;
                        float u0 = c[mt][nt][half * 2 + 0];
                        float u1 = c[mt][nt][half * 2 + 1];
                        if (prestep) {
                            *(float2*)&WyD[g] = make_float2(u0, u1);
                        } else {
                            float2 w = *(const float2*)&WyD[g];
                            u0 += w.x; u1 += w.y;
                        }
                        const int cp = col >> 1;
                        s2[r * 256 + (cp ^ ((r & 3) << 2))] =
                            pack_split(softthr(u0, th), softthr(u1, th));
                    }
                }
        }
    };

    // ---- phase2: d = s2 @ G2^T ; fp32 -> out slab, packed -> Dp ----
    auto phase2 = [&](float* dst) {
        for (int nc = 0; nc < 2; ++nc) {
            float c[2][4][4];
#pragma unroll
            for (int mt = 0; mt < 2; ++mt)
#pragma unroll
                for (int nt = 0; nt < 4; ++nt)
#pragma unroll
                    for (int q = 0; q < 4; ++q) c[mt][nt][q] = 0.f;

            const uint2* Bgc = G2p + (size_t)(nc * NC) * (NDIM / 2);
            fillB(0, Bgc, NDIM / 2, 0);
            cp_commit();
            for (int kb = 0; kb < NDIM / KC; ++kb) {
                if (kb + 1 < NDIM / KC) {
                    fillB((kb + 1) & 1, Bgc, NDIM / 2, kb + 1);
                    cp_commit();
                    cp_wait<1>();
                } else {
                    cp_wait<0>();
                }
                __syncthreads();
                const int kbase = kb * KP;
                mma_block([&](int r, int kp) {
                    int cc = kbase + kp;
                    return s2[r * 256 + (cc ^ ((r & 3) << 2))];
                }, &BstU[(kb & 1) * BST_U2], c);
                __syncthreads();
            }
            // frags -> est (fp32, pitch 260) -> global fp32 + packed Dp
#pragma unroll
            for (int mt = 0; mt < 2; ++mt)
#pragma unroll
                for (int nt = 0; nt < 4; ++nt) {
                    const int col = wN * 32 + nt * 8 + 2 * lc;
                    const int r = wM * 32 + mt * 16 + lr;
                    *(float2*)&est[r * PE + col] = make_float2(c[mt][nt][0], c[mt][nt][1]);
                    *(float2*)&est[(r + 8) * PE + col] = make_float2(c[mt][nt][2], c[mt][nt][3]);
                }
            __syncthreads();
            for (int i = tid; i < ROWS * (NC / 4); i += 512) {
                int r = i >> 6, c4 = i & 63;
                float4 v = *(float4*)&est[r * PE + c4 * 4];
                *(float4*)&dst[(size_t)r * NDIM + nc * NC + c4 * 4] = v;
                uint2 p0 = pack_split(v.x, v.y);
                uint2 p1 = pack_split(v.z, v.w);
                *(uint4*)&Dp[(size_t)(r0 + r) * (NDIM / 2) + (nc * NC) / 2 + c4 * 2] =
                    make_uint4(p0.x, p0.y, p1.x, p1.y);
            }
            __syncthreads();
        }
    };

    // ---- recurrence ----
    // prestep: WyD = y @ GW^T ; s0 = softthr(WyD)
    phase1(yp + (size_t)r0 * (MDIM / 2), MDIM / 2, MDIM / KC, GWp, MDIM / 2, true);
    __syncthreads();

    for (int t = 1; t <= NITER; ++t) {
        phase2(out + (size_t)t * slab + (size_t)r0 * NDIM);
        __syncthreads();
        if (t < NITER) {
            phase1(Dp + (size_t)r0 * (NDIM / 2), NDIM / 2, NDIM / KC,
                   G1p, NDIM / 2, false);
            __syncthreads();
        }
    }
}

// ---------------------------------------------------------------------------
// Host side
// ---------------------------------------------------------------------------
extern "C" void kernel_launch(void* const* d_in, const int* in_sizes, int n_in,
                              void* d_out, int out_size) {
    const float* y   = (const float*)d_in[0];
    const float* S   = (const float*)d_in[1];
    const float* W   = (const float*)d_in[2];
    const float* D   = (const float*)d_in[3];
    const float* thr = (const float*)d_in[4];
    float* out = (float*)d_out;

    void *pG1, *pG2, *pGW, *pyp, *pDp, *pWyD;
    cudaGetSymbolAddress(&pG1, g_G1p);
    cudaGetSymbolAddress(&pG2, g_G2p);
    cudaGetSymbolAddress(&pGW, g_GWp);
    cudaGetSymbolAddress(&pyp, g_yp);
    cudaGetSymbolAddress(&pDp, g_Dp);
    cudaGetSymbolAddress(&pWyD, g_WyD);

    cudaFuncSetAttribute(k_ista, cudaFuncAttributeMaxDynamicSharedMemorySize, SMEM_BYTES);

    // Precompute packed G2 = D^T, G1 = D@S, GW = D@W, y
    k_transpose_pack<<<dim3(16, 32), dim3(16, 16)>>>(D, (uint2*)pG2);
    k_small_gemm_pack<<<dim3(32, 32), dim3(16, 16)>>>(D, S, (uint2*)pG1, NDIM, NDIM);
    k_small_gemm_pack<<<dim3(16, 32), dim3(16, 16)>>>(D, W, (uint2*)pGW, MDIM, NDIM);
    k_split_pack<<<(B_ROWS * MDIM / 2) / 256, 256>>>(y, (uint2*)pyp);

    // One persistent kernel runs the whole recurrence.
    k_ista<<<B_ROWS / ROWS, 512, SMEM_BYTES>>>(
        thr, out, (const uint2*)pG1, (const uint2*)pG2, (const uint2*)pGW,
        (const uint2*)pyp, (uint2*)pDp, (float*)pWyD);
}